// round 2
// baseline (speedup 1.0000x reference)
#include <cuda_runtime.h>
#include <math_constants.h>

// Problem constants
#define BB 4
#define SS 2048
#define DM 512
#define HH 8
#define DD 64
#define LEFTK 128
#define RIGHTK 128

// Scratch (allocation-free: __device__ globals)
__device__ float g_Q[BB * SS * DM];
__device__ float g_K[BB * SS * DM];
__device__ float g_V[BB * SS * DM];
__device__ float g_C[BB * SS * DM];
__device__ float g_meanV[BB * DM];
#define MV_CHUNKS 16
__device__ float g_meanV_part[BB * MV_CHUNKS * DM];

// ---------------------------------------------------------------------------
// SGEMM: C[M=8192, N=512] = A[M,512] @ W[512,512] + bias[512]
// BM=128, BN=128, BK=16, 256 threads, 8x8 per thread.
// Double-buffered shared memory: prefetch K-tile k0+16 into registers while
// computing on tile k0; one __syncthreads per K-step.
// ---------------------------------------------------------------------------
#define GTILE (16 * 132)   // one smem buffer (BK x 132-padded)

__global__ __launch_bounds__(256) void sgemm_bias_kernel(
    const float* __restrict__ A, const float* __restrict__ W,
    const float* __restrict__ bias, float* __restrict__ C)
{
    extern __shared__ __align__(16) float sh[];
    // layout: As0 | As1 | Bs0 | Bs1
    float* Asb[2] = { sh,             sh + GTILE };
    float* Bsb[2] = { sh + 2 * GTILE, sh + 3 * GTILE };

    const int t  = threadIdx.x;
    const int tx = t & 15;
    const int ty = t >> 4;
    const int m0 = blockIdx.x * 128;
    const int n0 = blockIdx.y * 128;

    float acc[8][8];
#pragma unroll
    for (int i = 0; i < 8; i++)
#pragma unroll
        for (int j = 0; j < 8; j++) acc[i][j] = 0.f;

    // A loader mapping: row am = t>>1 (0..127), k offset ak = (t&1)*8
    const int am = t >> 1;
    const int ak = (t & 1) * 8;
    // B loader mapping: rows br, br+8; col group bc
    const int br = t >> 5;
    const int bc = (t & 31) * 4;

    const float* Aptr = A + (size_t)(m0 + am) * DM + ak;
    const float* Wptr = W + (size_t)br * DM + n0 + bc;

    float4 a0, a1, b0, b1;
    // preload k0 = 0
    a0 = *(const float4*)&Aptr[0];
    a1 = *(const float4*)&Aptr[4];
    b0 = *(const float4*)&Wptr[0];
    b1 = *(const float4*)&Wptr[8 * DM];
    {
        float* As = Asb[0]; float* Bs = Bsb[0];
        As[(ak + 0) * 132 + am] = a0.x; As[(ak + 1) * 132 + am] = a0.y;
        As[(ak + 2) * 132 + am] = a0.z; As[(ak + 3) * 132 + am] = a0.w;
        As[(ak + 4) * 132 + am] = a1.x; As[(ak + 5) * 132 + am] = a1.y;
        As[(ak + 6) * 132 + am] = a1.z; As[(ak + 7) * 132 + am] = a1.w;
        *(float4*)&Bs[br * 132 + bc]       = b0;
        *(float4*)&Bs[(br + 8) * 132 + bc] = b1;
    }
    __syncthreads();

    int cur = 0;
    for (int k0 = 16; k0 < DM; k0 += 16) {
        // issue next-tile global loads (overlap with compute below)
        a0 = *(const float4*)&Aptr[k0];
        a1 = *(const float4*)&Aptr[k0 + 4];
        b0 = *(const float4*)&Wptr[(size_t)k0 * DM];
        b1 = *(const float4*)&Wptr[(size_t)(k0 + 8) * DM];

        {
            const float* As = Asb[cur]; const float* Bs = Bsb[cur];
#pragma unroll
            for (int kk = 0; kk < 16; kk++) {
                float a[8], b[8];
                *(float4*)&a[0] = *(const float4*)&As[kk * 132 + ty * 8];
                *(float4*)&a[4] = *(const float4*)&As[kk * 132 + ty * 8 + 4];
                *(float4*)&b[0] = *(const float4*)&Bs[kk * 132 + tx * 8];
                *(float4*)&b[4] = *(const float4*)&Bs[kk * 132 + tx * 8 + 4];
#pragma unroll
                for (int i = 0; i < 8; i++)
#pragma unroll
                    for (int j = 0; j < 8; j++)
                        acc[i][j] += a[i] * b[j];
            }
        }
        const int nxt = cur ^ 1;
        {
            float* As = Asb[nxt]; float* Bs = Bsb[nxt];
            As[(ak + 0) * 132 + am] = a0.x; As[(ak + 1) * 132 + am] = a0.y;
            As[(ak + 2) * 132 + am] = a0.z; As[(ak + 3) * 132 + am] = a0.w;
            As[(ak + 4) * 132 + am] = a1.x; As[(ak + 5) * 132 + am] = a1.y;
            As[(ak + 6) * 132 + am] = a1.z; As[(ak + 7) * 132 + am] = a1.w;
            *(float4*)&Bs[br * 132 + bc]       = b0;
            *(float4*)&Bs[(br + 8) * 132 + bc] = b1;
        }
        __syncthreads();
        cur = nxt;
    }

    // last tile
    {
        const float* As = Asb[cur]; const float* Bs = Bsb[cur];
#pragma unroll
        for (int kk = 0; kk < 16; kk++) {
            float a[8], b[8];
            *(float4*)&a[0] = *(const float4*)&As[kk * 132 + ty * 8];
            *(float4*)&a[4] = *(const float4*)&As[kk * 132 + ty * 8 + 4];
            *(float4*)&b[0] = *(const float4*)&Bs[kk * 132 + tx * 8];
            *(float4*)&b[4] = *(const float4*)&Bs[kk * 132 + tx * 8 + 4];
#pragma unroll
            for (int i = 0; i < 8; i++)
#pragma unroll
                for (int j = 0; j < 8; j++)
                    acc[i][j] += a[i] * b[j];
        }
    }

#pragma unroll
    for (int i = 0; i < 8; i++) {
        const int m = m0 + ty * 8 + i;
#pragma unroll
        for (int j = 0; j < 8; j += 4) {
            const int n = n0 + tx * 8 + j;
            float4 o;
            o.x = acc[i][j]     + __ldg(&bias[n]);
            o.y = acc[i][j + 1] + __ldg(&bias[n + 1]);
            o.z = acc[i][j + 2] + __ldg(&bias[n + 2]);
            o.w = acc[i][j + 3] + __ldg(&bias[n + 3]);
            *(float4*)&C[(size_t)m * DM + n] = o;
        }
    }
}

// ---------------------------------------------------------------------------
// meanV two-stage: partials over 128-row chunks (64 blocks), then reduce.
// ---------------------------------------------------------------------------
__global__ void meanv_part_kernel(const float* __restrict__ V, float* __restrict__ part)
{
    const int b  = blockIdx.x;
    const int ch = blockIdx.y;
    const int c  = threadIdx.x;  // 512
    const int r0 = ch * (SS / MV_CHUNKS);
    const float* p = V + ((size_t)b * SS + r0) * DM + c;
    float s = 0.f;
#pragma unroll 4
    for (int j = 0; j < SS / MV_CHUNKS; j++) s += p[(size_t)j * DM];
    part[(b * MV_CHUNKS + ch) * DM + c] = s;
}

__global__ void meanv_reduce_kernel(const float* __restrict__ part, float* __restrict__ meanV)
{
    const int b = blockIdx.x;
    const int c = threadIdx.x;
    float s = 0.f;
#pragma unroll
    for (int ch = 0; ch < MV_CHUNKS; ch++)
        s += part[(b * MV_CHUNKS + ch) * DM + c];
    meanV[b * DM + c] = s * (1.0f / (float)SS);
}

// ---------------------------------------------------------------------------
// Banded attention. 1 thread = 1 query (q, acc[64] in regs). A block of 128
// queries for one (b,h) sweeps the union key band with a warp-UNIFORM key
// index so all K/V shared loads are broadcasts. Online softmax in 8-key
// subtiles. Keys j valid iff j in [i-128, i+128] and j < x_len[b].
// ---------------------------------------------------------------------------
#define BQ 128
#define KCH 128
#define KST 68   // row stride in floats (16B-aligned for float4)

__global__ __launch_bounds__(128) void attn_kernel(
    const float* __restrict__ Q, const float* __restrict__ K,
    const float* __restrict__ V, const float* __restrict__ meanV,
    const int* __restrict__ xlen, float* __restrict__ C)
{
    extern __shared__ __align__(16) float sh[];
    float* Ks = sh;
    float* Vs = sh + KCH * KST;

    const int b  = blockIdx.z;
    const int h  = blockIdx.y;
    const int q0 = blockIdx.x * BQ;
    const int t  = threadIdx.x;
    const int i  = q0 + t;
    const int xl = xlen[b];

    float q[64];
    {
        const float* qp = Q + ((size_t)(b * SS + i)) * DM + h * DD;
#pragma unroll
        for (int d = 0; d < 64; d += 4) {
            float4 v4 = *(const float4*)&qp[d];
            q[d]     = v4.x * 0.125f;   // 1/sqrt(64)
            q[d + 1] = v4.y * 0.125f;
            q[d + 2] = v4.z * 0.125f;
            q[d + 3] = v4.w * 0.125f;
        }
    }
    float acc[64];
#pragma unroll
    for (int d = 0; d < 64; d++) acc[d] = 0.f;
    float m = -CUDART_INF_F, l = 0.f;

    const int jlo = max(0, i - LEFTK);
    const int jhi = min(min(SS, i + RIGHTK + 1), xl);  // exclusive end of valid keys
    const bool fully_masked = (jlo >= xl);

    const int cmin = max(0, q0 - LEFTK);
    int cmax = min(SS, q0 + BQ + RIGHTK);
    if (cmax > xl) cmax = xl;  // keys >= xl invalid for every thread

    for (int jc = cmin; jc < cmax; jc += KCH) {
        const int rows = min(KCH, cmax - jc);
        __syncthreads();
        for (int idx = t; idx < rows * 16; idx += BQ) {
            const int r  = idx >> 4;
            const int dq = (idx & 15) << 2;
            const size_t g = ((size_t)(b * SS + jc + r)) * DM + h * DD + dq;
            *(float4*)&Ks[r * KST + dq] = *(const float4*)&K[g];
            *(float4*)&Vs[r * KST + dq] = *(const float4*)&V[g];
        }
        __syncthreads();

        for (int j8 = jc; j8 < jc + rows; j8 += 8) {
            const int n8 = min(8, jc + rows - j8);  // uniform across block
            float e[8];
            float mloc = -CUDART_INF_F;
#pragma unroll
            for (int jj = 0; jj < 8; jj++) {
                e[jj] = -CUDART_INF_F;
                if (jj < n8) {
                    const float* kr = &Ks[(j8 - jc + jj) * KST];
                    float d0 = 0.f, d1 = 0.f;
#pragma unroll
                    for (int d = 0; d < 64; d += 8) {
                        float4 k4 = *(const float4*)&kr[d];
                        float4 k5 = *(const float4*)&kr[d + 4];
                        d0 += q[d]     * k4.x + q[d + 1] * k4.y
                            + q[d + 2] * k4.z + q[d + 3] * k4.w;
                        d1 += q[d + 4] * k5.x + q[d + 5] * k5.y
                            + q[d + 6] * k5.z + q[d + 7] * k5.w;
                    }
                    const int j = j8 + jj;
                    if (j >= jlo && j < jhi) e[jj] = d0 + d1;
                    mloc = fmaxf(mloc, e[jj]);
                }
            }
            const float mn = fmaxf(m, mloc);
            if (mn == -CUDART_INF_F) continue;  // nothing valid yet (no syncs inside)
            const float corr = __expf(m - mn);  // exp(-inf)=0 handles first tile
            m = mn;
            l *= corr;
#pragma unroll
            for (int d = 0; d < 64; d++) acc[d] *= corr;
#pragma unroll
            for (int jj = 0; jj < 8; jj++) {
                if (jj < n8) {  // n8 uniform -> no divergence
                    const float p = __expf(e[jj] - mn);  // invalid -> exp(-inf)=0
                    l += p;
                    const float* vr = &Vs[(j8 - jc + jj) * KST];
#pragma unroll
                    for (int d = 0; d < 64; d += 4) {
                        float4 v4 = *(const float4*)&vr[d];
                        acc[d]     += p * v4.x;
                        acc[d + 1] += p * v4.y;
                        acc[d + 2] += p * v4.z;
                        acc[d + 3] += p * v4.w;
                    }
                }
            }
        }
    }

    float* cp = C + ((size_t)(b * SS + i)) * DM + h * DD;
    if (fully_masked) {
        // fp32 reference: all energies collapse to exactly -1e30 -> uniform
        // softmax over ALL S keys -> ctx = mean of V over the sequence.
        const float* mv = meanV + b * DM + h * DD;
#pragma unroll
        for (int d = 0; d < 64; d += 4)
            *(float4*)&cp[d] = *(const float4*)&mv[d];
    } else {
        const float inv = 1.0f / l;
#pragma unroll
        for (int d = 0; d < 64; d += 4) {
            float4 o;
            o.x = acc[d] * inv;     o.y = acc[d + 1] * inv;
            o.z = acc[d + 2] * inv; o.w = acc[d + 3] * inv;
            *(float4*)&cp[d] = o;
        }
    }
}

// ---------------------------------------------------------------------------
// Launch
// ---------------------------------------------------------------------------
extern "C" void kernel_launch(void* const* d_in, const int* in_sizes, int n_in,
                              void* d_out, int out_size)
{
    const float* x    = (const float*)d_in[0];
    const float* Wq   = (const float*)d_in[1];
    const float* bq   = (const float*)d_in[2];
    const float* Wk   = (const float*)d_in[3];
    const float* bk   = (const float*)d_in[4];
    const float* Wv   = (const float*)d_in[5];
    const float* bv   = (const float*)d_in[6];
    const float* Wo   = (const float*)d_in[7];
    const float* bo   = (const float*)d_in[8];
    const int*   xlen = (const int*)d_in[9];
    float* out = (float*)d_out;

    float *Qp, *Kp, *Vp, *Cp, *Mp, *MPp;
    cudaGetSymbolAddress((void**)&Qp, g_Q);
    cudaGetSymbolAddress((void**)&Kp, g_K);
    cudaGetSymbolAddress((void**)&Vp, g_V);
    cudaGetSymbolAddress((void**)&Cp, g_C);
    cudaGetSymbolAddress((void**)&Mp, g_meanV);
    cudaGetSymbolAddress((void**)&MPp, g_meanV_part);

    const int gsh = 4 * GTILE * (int)sizeof(float);  // 67584
    static int attr_done = 0;
    cudaFuncSetAttribute(sgemm_bias_kernel,
                         cudaFuncAttributeMaxDynamicSharedMemorySize, gsh);
    (void)attr_done;

    const dim3 ggrid((BB * SS) / 128, DM / 128);  // 64 x 4
    sgemm_bias_kernel<<<ggrid, 256, gsh>>>(x, Wq, bq, Qp);
    sgemm_bias_kernel<<<ggrid, 256, gsh>>>(x, Wk, bk, Kp);
    sgemm_bias_kernel<<<ggrid, 256, gsh>>>(x, Wv, bv, Vp);

    meanv_part_kernel<<<dim3(BB, MV_CHUNKS), DM>>>(Vp, MPp);
    meanv_reduce_kernel<<<BB, DM>>>(MPp, Mp);

    const int shbytes = 2 * KCH * KST * (int)sizeof(float);  // 69632
    cudaFuncSetAttribute(attn_kernel,
                         cudaFuncAttributeMaxDynamicSharedMemorySize, shbytes);
    attn_kernel<<<dim3(SS / BQ, HH, BB), BQ, shbytes>>>(Qp, Kp, Vp, Mp, xlen, Cp);

    sgemm_bias_kernel<<<ggrid, 256, gsh>>>(Cp, Wo, bo, out);
}

// round 17
// speedup vs baseline: 1.2570x; 1.2570x over previous
#include <cuda_runtime.h>
#include <math_constants.h>

// Problem constants
#define BB 4
#define SS 2048
#define DM 512
#define HH 8
#define DD 64
#define LEFTK 128
#define RIGHTK 128

typedef unsigned long long u64;

// Scratch (allocation-free: __device__ globals)
__device__ float g_Q[BB * SS * DM];
__device__ float g_K[BB * SS * DM];
__device__ float g_V[BB * SS * DM];
__device__ float g_C[BB * SS * DM];
__device__ float g_meanV[BB * DM];
#define MV_CHUNKS 64
__device__ float g_meanV_part[BB * MV_CHUNKS * DM];

// ---------------------------------------------------------------------------
// Packed f32x2 helpers (sm_103a): bit-exact IEEE fp32 op on each 32-bit lane.
// ---------------------------------------------------------------------------
__device__ __forceinline__ u64 pack2_dup(float x) {
    u64 r; asm("mov.b64 %0, {%1, %2};" : "=l"(r) : "f"(x), "f"(x)); return r;
}
__device__ __forceinline__ void fma2(u64& d, u64 a, u64 b) {
    asm("fma.rn.f32x2 %0, %1, %2, %0;" : "+l"(d) : "l"(a), "l"(b));
}
__device__ __forceinline__ void mul2(u64& d, u64 a) {
    asm("mul.rn.f32x2 %0, %0, %1;" : "+l"(d) : "l"(a));
}
__device__ __forceinline__ void unpack2(u64 v, float& lo, float& hi) {
    asm("mov.b64 {%0, %1}, %2;" : "=f"(lo), "=f"(hi) : "l"(v));
}

// ---------------------------------------------------------------------------
// cp.async helpers
// ---------------------------------------------------------------------------
__device__ __forceinline__ void cp16(void* smem_dst, const void* gsrc) {
    unsigned s = (unsigned)__cvta_generic_to_shared(smem_dst);
    asm volatile("cp.async.cg.shared.global [%0], [%1], 16;\n" :: "r"(s), "l"(gsrc));
}
__device__ __forceinline__ void cp_commit() {
    asm volatile("cp.async.commit_group;\n");
}
__device__ __forceinline__ void cp_wait0() {
    asm volatile("cp.async.wait_group 0;\n");
}

// ---------------------------------------------------------------------------
// SGEMM: C[M, N=512] = A[M,512] @ W[512,512] + bias. BM=BN=128, BK=16,
// 256 threads, 8x8/thread. 2-stage cp.async pipeline; inner product uses
// packed fma.rn.f32x2 (2 FMA/instr, fp32-exact) -> half the FFMA issue.
// ---------------------------------------------------------------------------
#define APAD 20
#define BPAD 132

__device__ __forceinline__ void issue_tile(
    const float* __restrict__ A, const float* __restrict__ W,
    int m0, int n0, int k0, float* AmB, float* BsB, int t)
{
    const int r  = t >> 1;
    const int c0 = (t & 1) * 2;
    cp16(&AmB[r * APAD + c0 * 4],     &A[(size_t)(m0 + r) * DM + k0 + c0 * 4]);
    cp16(&AmB[r * APAD + c0 * 4 + 4], &A[(size_t)(m0 + r) * DM + k0 + c0 * 4 + 4]);
    const int br = t >> 5;
    const int bc = (t & 31) * 4;
    cp16(&BsB[br * BPAD + bc],       &W[(size_t)(k0 + br) * DM + n0 + bc]);
    cp16(&BsB[(br + 8) * BPAD + bc], &W[(size_t)(k0 + br + 8) * DM + n0 + bc]);
    cp_commit();
}

__device__ __forceinline__ void sgemm_body(
    const float* __restrict__ A, const float* __restrict__ W,
    const float* __restrict__ bias, float* __restrict__ C,
    int m0, int n0)
{
    __shared__ __align__(16) float Am[2][128 * APAD];
    __shared__ __align__(16) float Bs[2][16 * BPAD];

    const int t  = threadIdx.x;
    const int tx = t & 15;
    const int ty = t >> 4;

    u64 acc2[8][4];
#pragma unroll
    for (int i = 0; i < 8; i++)
#pragma unroll
        for (int j = 0; j < 4; j++) acc2[i][j] = 0ull;

    issue_tile(A, W, m0, n0, 0, Am[0], Bs[0], t);

    const int NIT = DM / 16;  // 32
    for (int it = 0; it < NIT; it++) {
        cp_wait0();
        __syncthreads();
        if (it + 1 < NIT)
            issue_tile(A, W, m0, n0, (it + 1) * 16, Am[(it + 1) & 1], Bs[(it + 1) & 1], t);

        const float* Ab = Am[it & 1];
        const float* Bb = Bs[it & 1];
#pragma unroll
        for (int kk = 0; kk < 16; kk++) {
            __align__(16) u64 bp[4];
            *(float4*)&bp[0] = *(const float4*)&Bb[kk * BPAD + tx * 8];
            *(float4*)&bp[2] = *(const float4*)&Bb[kk * BPAD + tx * 8 + 4];
#pragma unroll
            for (int i = 0; i < 8; i++) {
                const u64 aa = pack2_dup(Ab[(ty * 8 + i) * APAD + kk]);
                fma2(acc2[i][0], aa, bp[0]);
                fma2(acc2[i][1], aa, bp[1]);
                fma2(acc2[i][2], aa, bp[2]);
                fma2(acc2[i][3], aa, bp[3]);
            }
        }
    }

#pragma unroll
    for (int i = 0; i < 8; i++) {
        const int m = m0 + ty * 8 + i;
#pragma unroll
        for (int j = 0; j < 2; j++) {
            const int n = n0 + tx * 8 + j * 4;
            float4 o;
            unpack2(acc2[i][j * 2],     o.x, o.y);
            unpack2(acc2[i][j * 2 + 1], o.z, o.w);
            o.x += __ldg(&bias[n]);
            o.y += __ldg(&bias[n + 1]);
            o.z += __ldg(&bias[n + 2]);
            o.w += __ldg(&bias[n + 3]);
            *(float4*)&C[(size_t)m * DM + n] = o;
        }
    }
}

__global__ __launch_bounds__(256) void sgemm_bias_kernel(
    const float* __restrict__ A, const float* __restrict__ W,
    const float* __restrict__ bias, float* __restrict__ C)
{
    sgemm_body(A, W, bias, C, blockIdx.x * 128, blockIdx.y * 128);
}

__global__ __launch_bounds__(256) void sgemm_qkv_kernel(
    const float* __restrict__ A,
    const float* __restrict__ W0, const float* __restrict__ W1, const float* __restrict__ W2,
    const float* __restrict__ b0, const float* __restrict__ b1, const float* __restrict__ b2,
    float* __restrict__ C0, float* __restrict__ C1, float* __restrict__ C2)
{
    const int z = blockIdx.z;
    const float* W = (z == 0) ? W0 : (z == 1) ? W1 : W2;
    const float* bi = (z == 0) ? b0 : (z == 1) ? b1 : b2;
    float* C = (z == 0) ? C0 : (z == 1) ? C1 : C2;
    sgemm_body(A, W, bi, C, blockIdx.x * 128, blockIdx.y * 128);
}

// ---------------------------------------------------------------------------
// meanV two-stage: 64 chunks of 32 rows (256 blocks), then reduce.
// ---------------------------------------------------------------------------
__global__ void meanv_part_kernel(const float* __restrict__ V, float* __restrict__ part)
{
    const int b  = blockIdx.x;
    const int ch = blockIdx.y;
    const int c  = threadIdx.x;  // 512
    const int r0 = ch * (SS / MV_CHUNKS);
    const float* p = V + ((size_t)b * SS + r0) * DM + c;
    float s = 0.f;
#pragma unroll
    for (int j = 0; j < SS / MV_CHUNKS; j++) s += p[(size_t)j * DM];
    part[(b * MV_CHUNKS + ch) * DM + c] = s;
}

__global__ void meanv_reduce_kernel(const float* __restrict__ part, float* __restrict__ meanV)
{
    const int b = blockIdx.x;
    const int c = threadIdx.x;
    float s = 0.f;
#pragma unroll 8
    for (int ch = 0; ch < MV_CHUNKS; ch++)
        s += part[(b * MV_CHUNKS + ch) * DM + c];
    meanV[b * DM + c] = s * (1.0f / (float)SS);
}

// ---------------------------------------------------------------------------
// Banded attention. 1 thread = 1 query; warp-uniform key sweep; online
// softmax. PV accumulate + rescale use packed f32x2 (bit-exact per lane).
// ---------------------------------------------------------------------------
#define BQ 128
#define KCH 128
#define KST 68   // row stride in floats (16B-aligned for float4)

__global__ __launch_bounds__(128) void attn_kernel(
    const float* __restrict__ Q, const float* __restrict__ K,
    const float* __restrict__ V, const float* __restrict__ meanV,
    const int* __restrict__ xlen, float* __restrict__ C)
{
    extern __shared__ __align__(16) float sh[];
    float* Ks = sh;
    float* Vs = sh + KCH * KST;

    const int b  = blockIdx.z;
    const int h  = blockIdx.y;
    const int q0 = blockIdx.x * BQ;
    const int t  = threadIdx.x;
    const int i  = q0 + t;
    const int xl = xlen[b];

    float q[64];
    {
        const float* qp = Q + ((size_t)(b * SS + i)) * DM + h * DD;
#pragma unroll
        for (int d = 0; d < 64; d += 4) {
            float4 v4 = *(const float4*)&qp[d];
            q[d]     = v4.x * 0.125f;   // 1/sqrt(64)
            q[d + 1] = v4.y * 0.125f;
            q[d + 2] = v4.z * 0.125f;
            q[d + 3] = v4.w * 0.125f;
        }
    }
    // acc packed: acc2[d] = {acc[2d], acc[2d+1]}
    u64 acc2[32];
#pragma unroll
    for (int d = 0; d < 32; d++) acc2[d] = 0ull;
    float m = -CUDART_INF_F, l = 0.f;

    const int jlo = max(0, i - LEFTK);
    const int jhi = min(min(SS, i + RIGHTK + 1), xl);
    const bool fully_masked = (jlo >= xl);

    const int cmin = max(0, q0 - LEFTK);
    int cmax = min(SS, q0 + BQ + RIGHTK);
    if (cmax > xl) cmax = xl;

    for (int jc = cmin; jc < cmax; jc += KCH) {
        const int rows = min(KCH, cmax - jc);
        __syncthreads();
        for (int idx = t; idx < rows * 16; idx += BQ) {
            const int r  = idx >> 4;
            const int dq = (idx & 15) << 2;
            const size_t g = ((size_t)(b * SS + jc + r)) * DM + h * DD + dq;
            *(float4*)&Ks[r * KST + dq] = *(const float4*)&K[g];
            *(float4*)&Vs[r * KST + dq] = *(const float4*)&V[g];
        }
        __syncthreads();

        for (int j8 = jc; j8 < jc + rows; j8 += 8) {
            const int n8 = min(8, jc + rows - j8);
            float e[8];
            float mloc = -CUDART_INF_F;
#pragma unroll
            for (int jj = 0; jj < 8; jj++) {
                e[jj] = -CUDART_INF_F;
                if (jj < n8) {
                    const float* kr = &Ks[(j8 - jc + jj) * KST];
                    float d0 = 0.f, d1 = 0.f;
#pragma unroll
                    for (int d = 0; d < 64; d += 8) {
                        float4 k4 = *(const float4*)&kr[d];
                        float4 k5 = *(const float4*)&kr[d + 4];
                        d0 += q[d]     * k4.x + q[d + 1] * k4.y
                            + q[d + 2] * k4.z + q[d + 3] * k4.w;
                        d1 += q[d + 4] * k5.x + q[d + 5] * k5.y
                            + q[d + 6] * k5.z + q[d + 7] * k5.w;
                    }
                    const int j = j8 + jj;
                    if (j >= jlo && j < jhi) e[jj] = d0 + d1;
                    mloc = fmaxf(mloc, e[jj]);
                }
            }
            const float mn = fmaxf(m, mloc);
            if (mn == -CUDART_INF_F) continue;
            const float corr = __expf(m - mn);
            m = mn;
            l *= corr;
            const u64 corr2 = pack2_dup(corr);
#pragma unroll
            for (int d = 0; d < 32; d++) mul2(acc2[d], corr2);
#pragma unroll
            for (int jj = 0; jj < 8; jj++) {
                if (jj < n8) {
                    const float p = __expf(e[jj] - mn);
                    l += p;
                    const u64 p2 = pack2_dup(p);
                    const float* vr = &Vs[(j8 - jc + jj) * KST];
#pragma unroll
                    for (int d = 0; d < 64; d += 4) {
                        __align__(16) u64 vp[2];
                        *(float4*)&vp[0] = *(const float4*)&vr[d];
                        fma2(acc2[d >> 1],       p2, vp[0]);
                        fma2(acc2[(d >> 1) + 1], p2, vp[1]);
                    }
                }
            }
        }
    }

    float* cp = C + ((size_t)(b * SS + i)) * DM + h * DD;
    if (fully_masked) {
        const float* mv = meanV + b * DM + h * DD;
#pragma unroll
        for (int d = 0; d < 64; d += 4)
            *(float4*)&cp[d] = *(const float4*)&mv[d];
    } else {
        const float inv = 1.0f / l;
#pragma unroll
        for (int d = 0; d < 64; d += 4) {
            float4 o;
            unpack2(acc2[d >> 1],       o.x, o.y);
            unpack2(acc2[(d >> 1) + 1], o.z, o.w);
            o.x *= inv; o.y *= inv; o.z *= inv; o.w *= inv;
            *(float4*)&cp[d] = o;
        }
    }
}

// ---------------------------------------------------------------------------
// Launch
// ---------------------------------------------------------------------------
extern "C" void kernel_launch(void* const* d_in, const int* in_sizes, int n_in,
                              void* d_out, int out_size)
{
    const float* x    = (const float*)d_in[0];
    const float* Wq   = (const float*)d_in[1];
    const float* bq   = (const float*)d_in[2];
    const float* Wk   = (const float*)d_in[3];
    const float* bk   = (const float*)d_in[4];
    const float* Wv   = (const float*)d_in[5];
    const float* bv   = (const float*)d_in[6];
    const float* Wo   = (const float*)d_in[7];
    const float* bo   = (const float*)d_in[8];
    const int*   xlen = (const int*)d_in[9];
    float* out = (float*)d_out;

    float *Qp, *Kp, *Vp, *Cp, *Mp, *MPp;
    cudaGetSymbolAddress((void**)&Qp, g_Q);
    cudaGetSymbolAddress((void**)&Kp, g_K);
    cudaGetSymbolAddress((void**)&Vp, g_V);
    cudaGetSymbolAddress((void**)&Cp, g_C);
    cudaGetSymbolAddress((void**)&Mp, g_meanV);
    cudaGetSymbolAddress((void**)&MPp, g_meanV_part);

    const dim3 qkvgrid((BB * SS) / 128, DM / 128, 3);  // 64 x 4 x 3
    sgemm_qkv_kernel<<<qkvgrid, 256>>>(x, Wq, Wk, Wv, bq, bk, bv, Qp, Kp, Vp);

    meanv_part_kernel<<<dim3(BB, MV_CHUNKS), DM>>>(Vp, MPp);
    meanv_reduce_kernel<<<BB, DM>>>(MPp, Mp);

    const int shbytes = 2 * KCH * KST * (int)sizeof(float);  // 69632
    cudaFuncSetAttribute(attn_kernel,
                         cudaFuncAttributeMaxDynamicSharedMemorySize, shbytes);
    attn_kernel<<<dim3(SS / BQ, HH, BB), BQ, shbytes>>>(Qp, Kp, Vp, Mp, xlen, Cp);

    const dim3 ogrid((BB * SS) / 128, DM / 128);  // 64 x 4
    sgemm_bias_kernel<<<ogrid, 256>>>(Cp, Wo, bo, out);
}